// round 8
// baseline (speedup 1.0000x reference)
#include <cuda_runtime.h>
#include <cuda_bf16.h>
#include <math.h>

#define N_NODES    500000
#define NUM_GRAPHS 1024

// Scratch (no cudaMalloc allowed). BSS-zeroed at load; self-cleaning per call.
__device__ float g_agg[N_NODES * 4];      // 8 MB, L2-resident

// ---------------------------------------------------------------------------
// Kernel 1: edge scatter  agg[dst] += x[src]   (R2-optimal config: 4/thread)
// Bound by L2 sector-op rate: 2 random 16B ops per edge (gather + red.v4).
// ---------------------------------------------------------------------------
__global__ void __launch_bounds__(256) k_edge(const float4* __restrict__ x,
                                              const int*    __restrict__ src,
                                              const int*    __restrict__ dst,
                                              int E) {
    int q  = blockIdx.x * blockDim.x + threadIdx.x;   // quad index
    int Eq = E >> 2;                                   // full quads

    if (q < Eq) {
        int4 s4 = __ldcs(reinterpret_cast<const int4*>(src) + q);
        int4 d4 = __ldcs(reinterpret_cast<const int4*>(dst) + q);

        float4 v0 = __ldg(x + s4.x);
        float4 v1 = __ldg(x + s4.y);
        float4 v2 = __ldg(x + s4.z);
        float4 v3 = __ldg(x + s4.w);

        asm volatile("red.global.add.v4.f32 [%0], {%1, %2, %3, %4};"
                     :: "l"(&g_agg[(size_t)d4.x * 4]),
                        "f"(v0.x), "f"(v0.y), "f"(v0.z), "f"(v0.w) : "memory");
        asm volatile("red.global.add.v4.f32 [%0], {%1, %2, %3, %4};"
                     :: "l"(&g_agg[(size_t)d4.y * 4]),
                        "f"(v1.x), "f"(v1.y), "f"(v1.z), "f"(v1.w) : "memory");
        asm volatile("red.global.add.v4.f32 [%0], {%1, %2, %3, %4};"
                     :: "l"(&g_agg[(size_t)d4.z * 4]),
                        "f"(v2.x), "f"(v2.y), "f"(v2.z), "f"(v2.w) : "memory");
        asm volatile("red.global.add.v4.f32 [%0], {%1, %2, %3, %4};"
                     :: "l"(&g_agg[(size_t)d4.w * 4]),
                        "f"(v3.x), "f"(v3.y), "f"(v3.z), "f"(v3.w) : "memory");
    } else if (q == Eq) {
        for (int i = Eq * 4; i < E; i++) {
            int s = __ldg(src + i);
            int d = __ldg(dst + i);
            float4 v = __ldg(x + s);
            asm volatile("red.global.add.v4.f32 [%0], {%1, %2, %3, %4};"
                         :: "l"(&g_agg[(size_t)d * 4]),
                            "f"(v.x), "f"(v.y), "f"(v.z), "f"(v.w) : "memory");
        }
    }
}

// ---------------------------------------------------------------------------
// Warp-cooperative lower_bound over sorted batch[]: 33-ary search, 4 rounds.
// Returns first index i with batch[i] >= key (or N if none).
// ---------------------------------------------------------------------------
__device__ __forceinline__ int warp_lower_bound(const int* __restrict__ batch,
                                                int key, unsigned lane) {
    int lo = 0, hi = N_NODES;                 // answer in [lo, hi]
    while (hi - lo > 32) {
        long long range = hi - lo;
        int p = lo + (int)((range * (long long)(lane + 1)) / 33);
        int pred = (__ldg(batch + p) < key) ? 1 : 0;
        unsigned bal = __ballot_sync(0xFFFFFFFFu, pred);
        int k = __popc(bal);                  // probes 0..k-1 are < key
        int pk   = __shfl_sync(0xFFFFFFFFu, p, (k < 32) ? k : 31);
        int pkm1 = __shfl_sync(0xFFFFFFFFu, p, (k > 0) ? k - 1 : 0);
        if (k > 0)  lo = pkm1 + 1;
        if (k < 32) hi = pk;
    }
    // final: linear probe of at most 32 slots
    int p = lo + (int)lane;
    int pred = (p < hi && __ldg(batch + p) < key) ? 1 : 0;
    unsigned bal = __ballot_sync(0xFFFFFFFFu, pred);
    return lo + __popc(bal);
}

// ---------------------------------------------------------------------------
// Kernel 2: one WARP per graph (batch sorted => contiguous node ranges).
// Streams coalesced x/agg over the range, MLP in registers, butterfly
// reduce, then lane 0 does mean + log_softmax and writes out[g] directly.
// No pool atomics, no g_sums/g_cnts, no k_pool launch.
// Self-cleaning: zeroes g_agg as it is consumed.
// ---------------------------------------------------------------------------
__global__ void __launch_bounds__(128) k_node(const float4* __restrict__ x,
                       const int*    __restrict__ batch,
                       const float*  __restrict__ eps_p,
                       const float*  __restrict__ W1,   // [4,16]
                       const float*  __restrict__ b1,   // [16]
                       const float*  __restrict__ W2,   // [16,4]
                       const float*  __restrict__ b2,   // [4]
                       float* __restrict__ out) {
    __shared__ float sW1[64], sb1[16], sW2[64], sb2[4];
    __shared__ float seps;
    int t = threadIdx.x;
    if (t < 64)              sW1[t]      = W1[t];
    if (t >= 64 && t < 128)  sW2[t - 64] = W2[t - 64];
    if (t < 16)              sb1[t]      = b1[t];
    if (t >= 16 && t < 20)   sb2[t - 16] = b2[t - 16];
    if (t == 20)             seps = 1.0f + eps_p[0];
    __syncthreads();

    unsigned lane = threadIdx.x & 31u;
    int g = blockIdx.x * 4 + (threadIdx.x >> 5);
    if (g >= NUM_GRAPHS) return;

    int start = warp_lower_bound(batch, g,     lane);
    int end   = warp_lower_bound(batch, g + 1, lane);

    float a0 = 0.f, a1 = 0.f, a2 = 0.f, a3 = 0.f;
    float4* aggv = reinterpret_cast<float4*>(g_agg);
    float se = seps;

    for (int i = start + (int)lane; i < end; i += 32) {
        float4 xv = __ldg(x + i);
        float4 av = aggv[i];
        aggv[i] = make_float4(0.f, 0.f, 0.f, 0.f);   // reset for next replay
        float h0 = se * xv.x + av.x;
        float h1 = se * xv.y + av.y;
        float h2 = se * xv.z + av.z;
        float h3 = se * xv.w + av.w;

        float o[4];
        #pragma unroll
        for (int k = 0; k < 4; k++) o[k] = sb2[k];
        #pragma unroll
        for (int j = 0; j < 16; j++) {
            float tj = sb1[j]
                     + h0 * sW1[0 * 16 + j]
                     + h1 * sW1[1 * 16 + j]
                     + h2 * sW1[2 * 16 + j]
                     + h3 * sW1[3 * 16 + j];
            tj = fmaxf(tj, 0.0f);
            #pragma unroll
            for (int k = 0; k < 4; k++) o[k] += tj * sW2[j * 4 + k];
        }
        a0 += fmaxf(o[0], 0.0f);
        a1 += fmaxf(o[1], 0.0f);
        a2 += fmaxf(o[2], 0.0f);
        a3 += fmaxf(o[3], 0.0f);
    }

    // Warp butterfly reduce the 4 accumulators.
    #pragma unroll
    for (int off = 16; off > 0; off >>= 1) {
        a0 += __shfl_xor_sync(0xFFFFFFFFu, a0, off);
        a1 += __shfl_xor_sync(0xFFFFFFFFu, a1, off);
        a2 += __shfl_xor_sync(0xFFFFFFFFu, a2, off);
        a3 += __shfl_xor_sync(0xFFFFFFFFu, a3, off);
    }

    if (lane == 0) {
        float c = fmaxf((float)(end - start), 1.0f);
        float v0 = a0 / c, v1 = a1 / c, v2 = a2 / c, v3 = a3 / c;
        float m = fmaxf(fmaxf(v0, v1), fmaxf(v2, v3));
        float s = expf(v0 - m) + expf(v1 - m) + expf(v2 - m) + expf(v3 - m);
        float l = m + logf(s);
        out[g * 4 + 0] = v0 - l;
        out[g * 4 + 1] = v1 - l;
        out[g * 4 + 2] = v2 - l;
        out[g * 4 + 3] = v3 - l;
    }
}

// ---------------------------------------------------------------------------
extern "C" void kernel_launch(void* const* d_in, const int* in_sizes, int n_in,
                              void* d_out, int out_size) {
    const float4* x   = (const float4*)d_in[0];
    const int*    ei  = (const int*)   d_in[1];   // [2, E]
    const int*    bat = (const int*)   d_in[2];
    const float*  eps = (const float*) d_in[3];
    const float*  W1  = (const float*) d_in[4];
    const float*  b1  = (const float*) d_in[5];
    const float*  W2  = (const float*) d_in[6];
    const float*  b2  = (const float*) d_in[7];
    float* out = (float*)d_out;

    int E = in_sizes[1] / 2;
    const int* src = ei;
    const int* dst = ei + E;

    int quads = E / 4 + 1;  // +1 thread for the tail
    k_edge<<<(quads + 255) / 256, 256>>>(x, src, dst, E);
    k_node<<<NUM_GRAPHS / 4, 128>>>(x, bat, eps, W1, b1, W2, b2, out);
}

// round 9
// speedup vs baseline: 1.1438x; 1.1438x over previous
#include <cuda_runtime.h>
#include <cuda_bf16.h>
#include <math.h>

#define N_NODES    500000
#define NUM_GRAPHS 1024

// Scratch (no cudaMalloc allowed). BSS-zeroed at load; self-cleaning per call.
__device__ float g_agg [N_NODES * 4];      // 8 MB, L2-resident
__device__ float g_sums[NUM_GRAPHS * 4];
__device__ float g_cnts[NUM_GRAPHS];

// ---------------------------------------------------------------------------
// Kernel 1: edge scatter  agg[dst] += x[src]   (R2-optimal: 4 edges/thread)
// Bound by L2 sector-op rate: 2 random 16B ops per edge (gather + red.v4).
// ---------------------------------------------------------------------------
__global__ void __launch_bounds__(256) k_edge(const float4* __restrict__ x,
                                              const int*    __restrict__ src,
                                              const int*    __restrict__ dst,
                                              int E) {
    int q  = blockIdx.x * blockDim.x + threadIdx.x;   // quad index
    int Eq = E >> 2;                                   // full quads

    if (q < Eq) {
        int4 s4 = __ldcs(reinterpret_cast<const int4*>(src) + q);
        int4 d4 = __ldcs(reinterpret_cast<const int4*>(dst) + q);

        float4 v0 = __ldg(x + s4.x);
        float4 v1 = __ldg(x + s4.y);
        float4 v2 = __ldg(x + s4.z);
        float4 v3 = __ldg(x + s4.w);

        asm volatile("red.global.add.v4.f32 [%0], {%1, %2, %3, %4};"
                     :: "l"(&g_agg[(size_t)d4.x * 4]),
                        "f"(v0.x), "f"(v0.y), "f"(v0.z), "f"(v0.w) : "memory");
        asm volatile("red.global.add.v4.f32 [%0], {%1, %2, %3, %4};"
                     :: "l"(&g_agg[(size_t)d4.y * 4]),
                        "f"(v1.x), "f"(v1.y), "f"(v1.z), "f"(v1.w) : "memory");
        asm volatile("red.global.add.v4.f32 [%0], {%1, %2, %3, %4};"
                     :: "l"(&g_agg[(size_t)d4.z * 4]),
                        "f"(v2.x), "f"(v2.y), "f"(v2.z), "f"(v2.w) : "memory");
        asm volatile("red.global.add.v4.f32 [%0], {%1, %2, %3, %4};"
                     :: "l"(&g_agg[(size_t)d4.w * 4]),
                        "f"(v3.x), "f"(v3.y), "f"(v3.z), "f"(v3.w) : "memory");
    } else if (q == Eq) {
        for (int i = Eq * 4; i < E; i++) {
            int s = __ldg(src + i);
            int d = __ldg(dst + i);
            float4 v = __ldg(x + s);
            asm volatile("red.global.add.v4.f32 [%0], {%1, %2, %3, %4};"
                         :: "l"(&g_agg[(size_t)d * 4]),
                            "f"(v.x), "f"(v.y), "f"(v.z), "f"(v.w) : "memory");
        }
    }
}

// ---------------------------------------------------------------------------
// Kernel 2: per-node MLP + pooled sum (one thread per node, R2 shape).
// Fast path for graph-uniform warps (~93%): butterfly reduce + 1 flush.
// Slow path (boundary/tail warps): warp-segmented scan.
// Self-cleaning: zeroes g_agg after consuming it.
// ---------------------------------------------------------------------------
__global__ void __launch_bounds__(256) k_node(const float4* __restrict__ x,
                       const int*    __restrict__ batch,
                       const float*  __restrict__ eps_p,
                       const float*  __restrict__ W1,   // [4,16] row-major
                       const float*  __restrict__ b1,   // [16]
                       const float*  __restrict__ W2,   // [16,4] row-major
                       const float*  __restrict__ b2) { // [4]
    __shared__ float sW1[64], sb1[16], sW2[64], sb2[4];
    __shared__ float seps;
    int t = threadIdx.x;
    if (t < 64)  sW1[t] = W1[t];
    if (t < 16)  sb1[t] = b1[t];
    if (t >= 64 && t < 128) sW2[t - 64] = W2[t - 64];
    if (t >= 128 && t < 132) sb2[t - 128] = b2[t - 128];
    if (t == 132) seps = 1.0f + eps_p[0];
    __syncthreads();

    int i = blockIdx.x * blockDim.x + threadIdx.x;

    float o0 = 0.f, o1 = 0.f, o2 = 0.f, o3 = 0.f, cnt = 0.f;
    int g = -1;

    if (i < N_NODES) {
        float4 xv = __ldg(x + i);
        float4* aggv = reinterpret_cast<float4*>(g_agg);
        float4 av = aggv[i];
        aggv[i] = make_float4(0.f, 0.f, 0.f, 0.f);   // reset for next replay
        float se = seps;
        float h0 = se * xv.x + av.x;
        float h1 = se * xv.y + av.y;
        float h2 = se * xv.z + av.z;
        float h3 = se * xv.w + av.w;

        float out4[4];
        #pragma unroll
        for (int k = 0; k < 4; k++) out4[k] = sb2[k];

        #pragma unroll
        for (int j = 0; j < 16; j++) {
            float tj = sb1[j]
                     + h0 * sW1[0 * 16 + j]
                     + h1 * sW1[1 * 16 + j]
                     + h2 * sW1[2 * 16 + j]
                     + h3 * sW1[3 * 16 + j];
            tj = fmaxf(tj, 0.0f);
            #pragma unroll
            for (int k = 0; k < 4; k++) out4[k] += tj * sW2[j * 4 + k];
        }
        o0 = fmaxf(out4[0], 0.0f);
        o1 = fmaxf(out4[1], 0.0f);
        o2 = fmaxf(out4[2], 0.0f);
        o3 = fmaxf(out4[3], 0.0f);
        cnt = 1.0f;
        g = __ldg(batch + i);
    }

    unsigned lane = threadIdx.x & 31u;
    int g0 = __shfl_sync(0xFFFFFFFFu, g, 0);

    if (__all_sync(0xFFFFFFFFu, g == g0)) {
        // ---- fast path: whole warp in one graph (incl. g0 >= 0 guaranteed
        //      when any work exists; if g0 < 0, warp is entirely out of range)
        #pragma unroll
        for (int off = 16; off > 0; off >>= 1) {
            o0  += __shfl_xor_sync(0xFFFFFFFFu, o0,  off);
            o1  += __shfl_xor_sync(0xFFFFFFFFu, o1,  off);
            o2  += __shfl_xor_sync(0xFFFFFFFFu, o2,  off);
            o3  += __shfl_xor_sync(0xFFFFFFFFu, o3,  off);
            cnt += __shfl_xor_sync(0xFFFFFFFFu, cnt, off);
        }
        if (lane == 0 && g0 >= 0) {
            atomicAdd(&g_sums[g0 * 4 + 0], o0);
            atomicAdd(&g_sums[g0 * 4 + 1], o1);
            atomicAdd(&g_sums[g0 * 4 + 2], o2);
            atomicAdd(&g_sums[g0 * 4 + 3], o3);
            atomicAdd(&g_cnts[g0], cnt);
        }
    } else {
        // ---- slow path: warp-segmented inclusive scan over sorted ids
        #pragma unroll
        for (int off = 1; off < 32; off <<= 1) {
            int   gg = __shfl_up_sync(0xFFFFFFFFu, g,   off);
            float t0 = __shfl_up_sync(0xFFFFFFFFu, o0,  off);
            float t1 = __shfl_up_sync(0xFFFFFFFFu, o1,  off);
            float t2 = __shfl_up_sync(0xFFFFFFFFu, o2,  off);
            float t3 = __shfl_up_sync(0xFFFFFFFFu, o3,  off);
            float tc = __shfl_up_sync(0xFFFFFFFFu, cnt, off);
            if (lane >= (unsigned)off && gg == g) {
                o0 += t0; o1 += t1; o2 += t2; o3 += t3; cnt += tc;
            }
        }
        int gnext = __shfl_down_sync(0xFFFFFFFFu, g, 1);
        bool last = (lane == 31u) || (gnext != g);
        if (last && g >= 0) {
            atomicAdd(&g_sums[g * 4 + 0], o0);
            atomicAdd(&g_sums[g * 4 + 1], o1);
            atomicAdd(&g_sums[g * 4 + 2], o2);
            atomicAdd(&g_sums[g * 4 + 3], o3);
            atomicAdd(&g_cnts[g], cnt);
        }
    }
}

// ---------------------------------------------------------------------------
// Kernel 3: mean pool + log_softmax; zeroes g_sums/g_cnts after consuming.
// ---------------------------------------------------------------------------
__global__ void k_pool(float* __restrict__ out) {
    int g = blockIdx.x * blockDim.x + threadIdx.x;
    if (g >= NUM_GRAPHS) return;
    float c = fmaxf(g_cnts[g], 1.0f);
    g_cnts[g] = 0.0f;
    float v[4];
    float m = -INFINITY;
    #pragma unroll
    for (int k = 0; k < 4; k++) {
        v[k] = g_sums[g * 4 + k] / c;
        g_sums[g * 4 + k] = 0.0f;
        m = fmaxf(m, v[k]);
    }
    float s = 0.0f;
    #pragma unroll
    for (int k = 0; k < 4; k++) s += expf(v[k] - m);
    float l = m + logf(s);
    #pragma unroll
    for (int k = 0; k < 4; k++) out[g * 4 + k] = v[k] - l;
}

// ---------------------------------------------------------------------------
extern "C" void kernel_launch(void* const* d_in, const int* in_sizes, int n_in,
                              void* d_out, int out_size) {
    const float4* x   = (const float4*)d_in[0];
    const int*    ei  = (const int*)   d_in[1];   // [2, E]
    const int*    bat = (const int*)   d_in[2];
    const float*  eps = (const float*) d_in[3];
    const float*  W1  = (const float*) d_in[4];
    const float*  b1  = (const float*) d_in[5];
    const float*  W2  = (const float*) d_in[6];
    const float*  b2  = (const float*) d_in[7];
    float* out = (float*)d_out;

    int E = in_sizes[1] / 2;
    const int* src = ei;
    const int* dst = ei + E;

    int quads = E / 4 + 1;  // +1 thread for the tail
    k_edge<<<(quads + 255) / 256, 256>>>(x, src, dst, E);
    k_node<<<(N_NODES + 255) / 256, 256>>>(x, bat, eps, W1, b1, W2, b2);
    k_pool<<<(NUM_GRAPHS + 255) / 256, 256>>>(out);
}